// round 9
// baseline (speedup 1.0000x reference)
#include <cuda_runtime.h>
#include <cuda_fp16.h>
#include <math.h>
#include <float.h>

// ---------------------------------------------------------------------------
// Scattering2D (J=2, L=8, 224x224) B=16, C=3  + global max pool + linear.
// FFTs: symmetric-pair 7-point DFT per lane x radix-2 shuffle FFT across lanes.
// Low-pass (phi) stages are exact spatial separable Gaussian blurs.
// Second-order fold fused into the final 224-pass (coalesced); fold in fp16.
// Chain smem image in fp16 -> 50.6KB/block -> 4 blocks/SM.
// ---------------------------------------------------------------------------

#define IMG224 (224*224)
#define IMG112 (112*112)

// ---- device global scratch -------------------------------------------------
__device__ float2  g_w224[224];
__device__ float   g_psi0[8*IMG224];     // j=0 Morlets @224
__device__ float   g_psi1[8*IMG224];     // j=1 Morlets @224
__device__ float   g_h0[21];             // spatial phi taps @224 (stride-4 path)
__device__ float   g_h1[11];             // spatial phi taps @112 (stride-2 path)
__device__ float2  g_xh[48*IMG224];      // fft2(x)
__device__ float2  g_s1buf[384*IMG224];  // scratch A
__device__ float2  g_s2buf[384*IMG224];  // scratch B
__device__ float   g_u1[384*IMG224];     // spatial u1 [TRANSPOSED layout]
__device__ __half2 g_foldh[3456*IMG112]; // prefolded 112x112 chain inputs (fp16)
__device__ float   g_feat[48*81];        // scattering features

// ---- complex helpers -------------------------------------------------------
__device__ __forceinline__ float2 cmul(float2 a, float2 b){
    return make_float2(fmaf(a.x,b.x,-a.y*b.y), fmaf(a.x,b.y, a.y*b.x));
}
template<bool INV>
__device__ __forceinline__ float2 twid(int t){
    float2 w = g_w224[t];
    if (INV) w.y = -w.y;
    return w;
}

// ---- core line FFT: symmetric-pair 7-pt DFT + radix-2 shuffle stages -------
template<int LOGG, bool INV>
__device__ __forceinline__ void fft_regs(float2 a[7], int gl){
    const int G  = 1 << LOGG;
    const int N  = 7 * G;
    const int ST = 224 / N;

    float2 w1 = twid<INV>(32), w2 = twid<INV>(64), w3 = twid<INV>(96);
    float2 a0 = a[0];
    float2 s1 = make_float2(a[1].x+a[6].x, a[1].y+a[6].y);
    float2 s2 = make_float2(a[2].x+a[5].x, a[2].y+a[5].y);
    float2 s3 = make_float2(a[3].x+a[4].x, a[3].y+a[4].y);
    float2 d1 = make_float2(a[1].x-a[6].x, a[1].y-a[6].y);
    float2 d2 = make_float2(a[2].x-a[5].x, a[2].y-a[5].y);
    float2 d3 = make_float2(a[3].x-a[4].x, a[3].y-a[4].y);

    float2 A[7];
    A[0] = make_float2(a0.x + s1.x + s2.x + s3.x,
                       a0.y + s1.y + s2.y + s3.y);
    {
        float px = fmaf(w1.x,s1.x, fmaf(w2.x,s2.x, fmaf(w3.x,s3.x, a0.x)));
        float py = fmaf(w1.x,s1.y, fmaf(w2.x,s2.y, fmaf(w3.x,s3.y, a0.y)));
        float qx = fmaf(w1.y,d1.x, fmaf(w2.y,d2.x, w3.y*d3.x));
        float qy = fmaf(w1.y,d1.y, fmaf(w2.y,d2.y, w3.y*d3.y));
        A[1] = make_float2(px - qy, py + qx);
        A[6] = make_float2(px + qy, py - qx);
    }
    {
        float px = fmaf(w2.x,s1.x, fmaf(w3.x,s2.x, fmaf(w1.x,s3.x, a0.x)));
        float py = fmaf(w2.x,s1.y, fmaf(w3.x,s2.y, fmaf(w1.x,s3.y, a0.y)));
        float qx = fmaf(w2.y,d1.x, fmaf(-w3.y,d2.x, -w1.y*d3.x));
        float qy = fmaf(w2.y,d1.y, fmaf(-w3.y,d2.y, -w1.y*d3.y));
        A[2] = make_float2(px - qy, py + qx);
        A[5] = make_float2(px + qy, py - qx);
    }
    {
        float px = fmaf(w3.x,s1.x, fmaf(w1.x,s2.x, fmaf(w2.x,s3.x, a0.x)));
        float py = fmaf(w3.x,s1.y, fmaf(w1.x,s2.y, fmaf(w2.x,s3.y, a0.y)));
        float qx = fmaf(w3.y,d1.x, fmaf(-w1.y,d2.x, w2.y*d3.x));
        float qy = fmaf(w3.y,d1.y, fmaf(-w1.y,d2.y, w2.y*d3.y));
        A[3] = make_float2(px - qy, py + qx);
        A[4] = make_float2(px + qy, py - qx);
    }

    #pragma unroll
    for (int k1 = 1; k1 < 7; k1++)
        A[k1] = cmul(A[k1], twid<INV>(gl * k1 * ST));

    #pragma unroll
    for (int m = G/2; m >= 1; m >>= 1){
        const int tstep = 224 / (2*m);
        float2 w = twid<INV>((gl & (m-1)) * tstep);
        bool up = (gl & m) != 0;
        #pragma unroll
        for (int k1 = 0; k1 < 7; k1++){
            float2 mine = A[k1];
            float2 oth;
            oth.x = __shfl_xor_sync(0xffffffffu, mine.x, m, 32);
            oth.y = __shfl_xor_sync(0xffffffffu, mine.y, m, 32);
            if (up) A[k1] = cmul(make_float2(oth.x - mine.x, oth.y - mine.y), w);
            else    A[k1] = make_float2(mine.x + oth.x, mine.y + oth.y);
        }
    }
    if (INV){
        const float s = 1.0f / (float)N;
        #pragma unroll
        for (int k1 = 0; k1 < 7; k1++){ A[k1].x *= s; A[k1].y *= s; }
    }
    #pragma unroll
    for (int k1 = 0; k1 < 7; k1++) a[k1] = A[k1];
}

__device__ __forceinline__ float blockMax448(float v){
    #pragma unroll
    for (int o = 16; o; o >>= 1) v = fmaxf(v, __shfl_xor_sync(0xffffffffu, v, o));
    __shared__ float red[14];
    int w = threadIdx.x >> 5;
    if ((threadIdx.x & 31) == 0) red[w] = v;
    __syncthreads();
    float m = -FLT_MAX;
    if (threadIdx.x == 0){
        #pragma unroll
        for (int i = 0; i < 14; i++) m = fmaxf(m, red[i]);
    }
    return m;
}

// ---- filter + twiddle + tap generation (every call) ------------------------
__device__ __forceinline__ float ffreq(int a){
    const float PI = 3.14159265358979f;
    return 2.0f*PI*(float)((a < 112) ? a : a - 224) / 224.0f;
}
__global__ void gen_filters_k(){
    int t = blockIdx.x*256 + threadIdx.x;
    const float PI = 3.14159265358979f;
    if (t < 224){
        double ang = -2.0*3.14159265358979323846*(double)t/224.0;
        g_w224[t] = make_float2((float)cos(ang), (float)sin(ang));
        return;
    }
    int u = t - 224;
    if (u < 2*8*IMG224){
        int j = u / (8*IMG224); int r = u - j*(8*IMG224);
        int l = r / IMG224;     int e = r - l*IMG224;
        int aa = e / 224, bb = e - aa*224;
        float wx = ffreq(aa), wy = ffreq(bb);
        float th = (float)l * (PI / 8.0f);
        float xi = (3.0f*PI/4.0f) / (float)(1 << j);
        float sg = 0.8f * (float)(1 << j);
        float ct = cosf(th), st = sinf(th);
        float uu =  ct*wx + st*wy;
        float vv = -st*wx + ct*wy;
        float vs = vv * 2.0f;                // / slant(=0.5)
        float s2 = 0.5f*sg*sg;
        float gab = expf(-s2*((uu-xi)*(uu-xi) + vs*vs));
        float gau = expf(-s2*(uu*uu + vs*vs));
        float kap = expf(-s2*xi*xi);
        float val = gab - kap*gau;
        if (j == 0) g_psi0[l*IMG224 + e] = val;
        else        g_psi1[l*IMG224 + e] = val;
        return;
    }
    u -= 2*8*IMG224;
    if (u < 32){
        int n, stride;
        if (u < 21){ n = u - 10; stride = 1; }              // g_h0 (224 grid)
        else       { n = u - 21 - 5; stride = 2; }          // g_h1 = h0 at even offsets
        float s = 0.f;
        for (int k = 0; k < 224; k++){
            float w = ffreq(k);
            float ang = 2.0f*PI*(float)(k*n*stride)/224.0f;
            s += expf(-1.28f*w*w) * cosf(ang);
        }
        s /= 224.0f;
        if (u < 21) g_h0[u] = s;
        else        g_h1[u-21] = s;
    }
}

// ---- @224 pass: 16 rows/block (512 thr), row FFT + coalesced transposed write
// MODE 0: x(real) fwd -> s1buf; 1: s1buf fwd -> xh; 2: xh*psi0 inv -> s1buf;
// MODE 3: inv + |.| -> u1, fwd -> s2buf
template<int MODE>
__global__ void __launch_bounds__(512) pass224_k(const float* __restrict__ xin){
    constexpr bool IN_REAL  = (MODE == 0);
    constexpr bool MUL_FILT = (MODE == 2);
    constexpr bool INV      = (MODE == 2 || MODE == 3);

    __shared__ float2 sbuf[16][225];
    int i    = blockIdx.y;
    int w    = threadIdx.x >> 5, lane = threadIdx.x & 31;
    int row  = blockIdx.x*16 + w;

    const float* inR = nullptr; const float2* inC = nullptr; const float* filt = nullptr;
    float2* outp = nullptr;
    if constexpr (MODE == 0){ inR = xin + (size_t)i*IMG224;            outp = g_s1buf; }
    if constexpr (MODE == 1){ inC = g_s1buf + (size_t)i*IMG224;        outp = g_xh;    }
    if constexpr (MODE == 2){ inC = g_xh + (size_t)(i >> 3)*IMG224;
                              filt = g_psi0 + (size_t)(i & 7)*IMG224;  outp = g_s1buf; }
    if constexpr (MODE == 3){ inC = g_s1buf + (size_t)i*IMG224;        outp = g_s2buf; }

    float2 a[7];
    #pragma unroll
    for (int n1 = 0; n1 < 7; n1++){
        int idx = row*224 + n1*32 + lane;
        float2 v;
        if constexpr (IN_REAL) v = make_float2(inR[idx], 0.f);
        else                   v = inC[idx];
        if constexpr (MUL_FILT){ float f = filt[idx]; v.x *= f; v.y *= f; }
        a[n1] = v;
    }
    fft_regs<5, INV>(a, lane);

    if constexpr (MODE == 3){
        // modulus (ifft2 complete) -> save spatial u1 -> forward FFT
        float* rb = (float*)&sbuf[w][0];
        int k2m = __brev((unsigned)lane) >> 27;
        #pragma unroll
        for (int k1 = 0; k1 < 7; k1++)
            rb[k1 + 7*k2m] = sqrtf(a[k1].x*a[k1].x + a[k1].y*a[k1].y);
        __syncwarp();
        float* u1o = g_u1 + (size_t)i*IMG224 + row*224;
        #pragma unroll
        for (int n1 = 0; n1 < 7; n1++){
            float v = rb[n1*32 + lane];
            u1o[n1*32 + lane] = v;
            a[n1] = make_float2(v, 0.f);
        }
        __syncwarp();
        fft_regs<5, false>(a, lane);
    }

    int k2 = __brev((unsigned)lane) >> 27;
    #pragma unroll
    for (int k1 = 0; k1 < 7; k1++) sbuf[w][k1 + 7*k2] = a[k1];
    __syncthreads();

    int rr   = threadIdx.x & 15;
    int kk   = threadIdx.x >> 4;
    int grow = blockIdx.x*16 + rr;
    float2* o = outp + (size_t)i*IMG224;
    #pragma unroll
    for (int it = 0; it < 7; it++){
        int k = kk + it*32;
        o[k*224 + grow] = sbuf[rr][k];
    }
}

// ---- merged pass4 + second-order fold (coalesced) --------------------------
__global__ void __launch_bounds__(512) pass4fold_k(){
    __shared__ float2 sbuf[16][225];
    int i    = blockIdx.y;
    int w    = threadIdx.x >> 5, lane = threadIdx.x & 31;
    int r0   = blockIdx.x * 8;
    int row  = (w < 8) ? (r0 + w) : (r0 + 112 + (w - 8));

    const float2* inC = g_s2buf + (size_t)i*IMG224;
    float2 a[7];
    #pragma unroll
    for (int n1 = 0; n1 < 7; n1++) a[n1] = inC[row*224 + n1*32 + lane];
    fft_regs<5, false>(a, lane);
    int k2 = __brev((unsigned)lane) >> 27;
    #pragma unroll
    for (int k1 = 0; k1 < 7; k1++) sbuf[w][k1 + 7*k2] = a[k1];
    __syncthreads();

    int outBase = 384 + i*8;
    for (int e = threadIdx.x; e < 896; e += 512){
        int aa = e % 112, bbl = e / 112;
        int b = r0 + bbl;
        float2 z00 = sbuf[bbl    ][aa      ];
        float2 z01 = sbuf[bbl    ][aa + 112];
        float2 z10 = sbuf[bbl + 8][aa      ];
        float2 z11 = sbuf[bbl + 8][aa + 112];
        int f00 =  b       *224 + aa;
        int f10 = (b + 112)*224 + aa;
        #pragma unroll
        for (int l2 = 0; l2 < 8; l2++){
            const float* f = g_psi1 + (size_t)l2*IMG224;
            float v00 = f[f00], v01 = f[f00 + 112], v10 = f[f10], v11 = f[f10 + 112];
            float ax = fmaf(z00.x,v00, fmaf(z01.x,v01, fmaf(z10.x,v10, z11.x*v11)));
            float ay = fmaf(z00.y,v00, fmaf(z01.y,v01, fmaf(z10.y,v10, z11.y*v11)));
            g_foldh[(size_t)(outBase + l2)*IMG112 + b*112 + aa] =
                __floats2half2_rn(ax*0.25f, ay*0.25f);
        }
    }
}

// ---- first-order fold (48 xh sources, all 8 l's) ---------------------------
__global__ void __launch_bounds__(512) fold2_k(){
    int s = blockIdx.y;                     // 0..47
    const float2* src = g_xh + (size_t)s*IMG224;
    int outBase = s*8;
    int base = blockIdx.x*1792;
    for (int e = base + threadIdx.x; e < base + 1792; e += 512){
        int aa = e/112, bb = e - aa*112;
        int i00 =  aa      *224 + bb, i01 =  aa      *224 + bb + 112;
        int i10 = (aa+112) *224 + bb, i11 = (aa+112) *224 + bb + 112;
        float2 s00 = src[i00], s01 = src[i01], s10 = src[i10], s11 = src[i11];
        #pragma unroll
        for (int l2 = 0; l2 < 8; l2++){
            const float* f = g_psi1 + (size_t)l2*IMG224;
            float f00 = f[i00], f01 = f[i01], f10 = f[i10], f11 = f[i11];
            float ax = fmaf(s00.x,f00, fmaf(s01.x,f01, fmaf(s10.x,f10, s11.x*f11)));
            float ay = fmaf(s00.y,f00, fmaf(s01.y,f01, fmaf(s10.y,f10, s11.y*f11)));
            g_foldh[(size_t)(outBase + l2)*IMG112 + e] =
                __floats2half2_rn(ax*0.25f, ay*0.25f);
        }
    }
}

// ---- fused @112 chain (fp16 smem image, 50.6KB): ifft2 -> |.| -> blur -> max
__device__ __forceinline__ void chain112(const __half2* __restrict__ fsrc,
                                         float* featOut){
    extern __shared__ __half2 smh[];    // 112 x 113 half2 (re,im) / (|z|,0)
    float* smf = (float*)smh;           // float overlay for hb stage
    __shared__ float sh_h[11];
    int tid = threadIdx.x;
    if (tid < 11) sh_h[tid] = g_h1[tid];
    int gl = tid & 15, grp = tid >> 4;  // 28 groups of 16

    // ifft2 row pass: global (fp16) -> fp32 FFT -> smem (fp16)
    for (int r = grp; r < 112; r += 28){
        float2 a[7];
        #pragma unroll
        for (int n1 = 0; n1 < 7; n1++)
            a[n1] = __half22float2(fsrc[r*112 + n1*16 + gl]);
        fft_regs<4, true>(a, gl);
        int k2 = __brev((unsigned)gl) >> 28;
        #pragma unroll
        for (int k1 = 0; k1 < 7; k1++)
            smh[r*113 + k1 + 7*k2] = __floats2half2_rn(a[k1].x, a[k1].y);
    }
    __syncthreads();
    // ifft2 col pass: fp32 FFT + modulus, stored in place as half2(|z|,0)
    for (int c = grp; c < 112; c += 28){
        float2 a[7];
        #pragma unroll
        for (int n1 = 0; n1 < 7; n1++)
            a[n1] = __half22float2(smh[(n1*16 + gl)*113 + c]);
        fft_regs<4, true>(a, gl);
        int k2 = __brev((unsigned)gl) >> 28;
        #pragma unroll
        for (int k1 = 0; k1 < 7; k1++){
            float2 z = a[k1];
            smh[(k1 + 7*k2)*113 + c] =
                __floats2half2_rn(sqrtf(z.x*z.x + z.y*z.y), 0.f);
        }
    }
    __syncthreads();

    // horizontal blur at stride-2 output columns: hb[r][c] (112 x 56)
    float rh[14];
    #pragma unroll
    for (int it = 0; it < 14; it++){
        int e = tid + it*448;
        int r = e % 112, c = e / 112;
        float acc = 0.f;
        #pragma unroll
        for (int d = 0; d < 11; d++){
            int cc = 2*c + d - 5;
            if (cc < 0) cc += 112; else if (cc >= 112) cc -= 112;
            acc = fmaf(sh_h[d], __low2float(smh[r*113 + cc]), acc);
        }
        rh[it] = acc;
    }
    __syncthreads();
    #pragma unroll
    for (int it = 0; it < 14; it++){
        int e = tid + it*448;
        int r = e % 112, c = e / 112;
        smf[r*57 + c] = rh[it];          // float hb overlay, pitch 57
    }
    __syncthreads();

    // vertical blur at stride-2 output rows + max
    float mx = -FLT_MAX;
    #pragma unroll
    for (int it = 0; it < 7; it++){
        int e = tid + it*448;
        int a = e / 56, b = e % 56;
        float acc = 0.f;
        #pragma unroll
        for (int d = 0; d < 11; d++){
            int rr = 2*a + d - 5;
            if (rr < 0) rr += 112; else if (rr >= 112) rr -= 112;
            acc = fmaf(sh_h[d], smf[rr*57 + b], acc);
        }
        mx = fmaxf(mx, acc);
    }
    float m = blockMax448(mx);
    if (tid == 0) *featOut = m;
}

// merged j1=1 first order + second order (3456 blocks)
__global__ void __launch_bounds__(448, 4) scatter2_k(){
    int i = blockIdx.x;
    int featIdx;
    if (i < 384){
        int bc = i >> 3, l = i & 7;
        featIdx = bc*81 + 9 + l;
    } else {
        int v = i - 384;
        int bc = v >> 6, l1 = (v >> 3) & 7, l2 = v & 7;
        featIdx = bc*81 + 17 + l1*8 + l2;
    }
    chain112(g_foldh + (size_t)i*IMG112, &g_feat[featIdx]);
}

// ---- s0 / s1(j1=0): spatial blur @224, stride 4, circular, + max -----------
__global__ void __launch_bounds__(448) blur224_k(const float* __restrict__ x){
    __shared__ float hb[224*57];        // 51KB
    __shared__ float sh_h[21];
    int i = blockIdx.x;                 // [0,48): s0 from x ; [48,432): s1 j1=0 from u1
    const float* src; int featIdx;
    if (i < 48){ src = x + (size_t)i*IMG224; featIdx = i*81; }
    else {
        int j = i - 48;
        src = g_u1 + (size_t)j*IMG224;
        featIdx = (j >> 3)*81 + 1 + (j & 7);
    }
    int tid = threadIdx.x;
    if (tid < 21) sh_h[tid] = g_h0[tid];
    __syncthreads();

    int rr = tid / 56, c = tid % 56;    // 8 rows x 56 cols per sweep
    for (int r0 = 0; r0 < 224; r0 += 8){
        int r = r0 + rr;
        float acc = 0.f;
        #pragma unroll
        for (int d = 0; d < 21; d++){
            int cc = 4*c + d - 10;
            if (cc < 0) cc += 224; else if (cc >= 224) cc -= 224;
            acc = fmaf(sh_h[d], __ldg(src + r*224 + cc), acc);
        }
        hb[r*57 + c] = acc;
    }
    __syncthreads();

    float mx = -FLT_MAX;
    #pragma unroll
    for (int it = 0; it < 7; it++){
        int e = tid + it*448;
        int a = e / 56, b = e % 56;
        float acc = 0.f;
        #pragma unroll
        for (int d = 0; d < 21; d++){
            int r2 = 4*a + d - 10;
            if (r2 < 0) r2 += 224; else if (r2 >= 224) r2 -= 224;
            acc = fmaf(sh_h[d], hb[r2*57 + b], acc);
        }
        mx = fmaxf(mx, acc);
    }
    float m = blockMax448(mx);
    if (tid == 0) g_feat[featIdx] = m;
}

// ---- final linear ----------------------------------------------------------
__global__ void linear_k(const float* __restrict__ W, const float* __restrict__ bias,
                         float* __restrict__ out){
    __shared__ float gs[243];
    int b = blockIdx.x;
    for (int k = threadIdx.x; k < 243; k += 256) gs[k] = g_feat[b*243 + k];
    __syncthreads();
    for (int o = threadIdx.x; o < 1000; o += 256){
        float acc = bias[o];
        const float* wr = W + o*243;
        #pragma unroll 3
        for (int k = 0; k < 243; k++) acc = fmaf(gs[k], wr[k], acc);
        out[b*1000 + o] = acc;
    }
}

// ---------------------------------------------------------------------------
extern "C" void kernel_launch(void* const* d_in, const int* in_sizes, int n_in,
                              void* d_out, int out_size){
    const float *x = nullptr, *W = nullptr, *bias = nullptr;
    for (int i = 0; i < n_in; i++){
        if      (in_sizes[i] == 16*3*224*224) x    = (const float*)d_in[i];
        else if (in_sizes[i] == 1000*243)     W    = (const float*)d_in[i];
        else if (in_sizes[i] == 1000)         bias = (const float*)d_in[i];
    }
    float* out = (float*)d_out;

    const int SM_CHAIN = 112*113*(int)sizeof(__half2);  // 50,624 B
    cudaFuncSetAttribute(scatter2_k, cudaFuncAttributeMaxDynamicSharedMemorySize, SM_CHAIN);

    int genTotal = 224 + 2*8*IMG224 + 32;
    gen_filters_k<<<(genTotal + 255)/256, 256>>>();

    pass224_k<0><<<dim3(14, 48),  512>>>(x);        // x -> s1buf (rows fwd)
    pass224_k<1><<<dim3(14, 48),  512>>>(nullptr);  // s1buf -> xh
    pass224_k<2><<<dim3(14, 384), 512>>>(nullptr);  // xh*psi0 -> s1buf (inv)
    pass224_k<3><<<dim3(14, 384), 512>>>(nullptr);  // inv + |.| -> u1, fwd -> s2buf

    pass4fold_k<<<dim3(14, 384), 512>>>();          // col FFT + fold*psi1 -> g_foldh
    fold2_k<<<dim3(7, 48), 512>>>();                // first-order folds -> g_foldh
    blur224_k<<<432, 448>>>(x);                     // s0 + s1(j1=0) via spatial blur
    scatter2_k<<<3456, 448, SM_CHAIN>>>();          // s1(j1=1) + s2
    linear_k<<<16, 256>>>(W, bias, out);
    (void)out_size;
}

// round 10
// speedup vs baseline: 1.0676x; 1.0676x over previous
#include <cuda_runtime.h>
#include <cuda_fp16.h>
#include <math.h>
#include <float.h>

// ---------------------------------------------------------------------------
// Scattering2D (J=2, L=8, 224x224) B=16, C=3  + global max pool + linear.
// FFTs: symmetric-pair 7-point DFT per lane x radix-2 shuffle FFT across lanes.
// Low-pass (phi) stages are exact spatial separable Gaussian blurs.
// Second-order fold fused into the final 224-pass (coalesced); fold in fp16.
// Chain: fp32 smem image, twiddles register-cached across the 8 FFTs/thread.
// ---------------------------------------------------------------------------

#define IMG224 (224*224)
#define IMG112 (112*112)

// ---- device global scratch -------------------------------------------------
__device__ float2  g_w224[224];
__device__ float   g_psi0[8*IMG224];     // j=0 Morlets @224
__device__ float   g_psi1[8*IMG224];     // j=1 Morlets @224
__device__ float   g_h0[21];             // spatial phi taps @224 (stride-4 path)
__device__ float   g_h1[11];             // spatial phi taps @112 (stride-2 path)
__device__ float2  g_xh[48*IMG224];      // fft2(x)
__device__ float2  g_s1buf[384*IMG224];  // scratch A
__device__ float2  g_s2buf[384*IMG224];  // scratch B
__device__ float   g_u1[384*IMG224];     // spatial u1 [TRANSPOSED layout]
__device__ __half2 g_foldh[3456*IMG112]; // prefolded 112x112 chain inputs (fp16)
__device__ float   g_feat[48*81];        // scattering features

// ---- complex helpers -------------------------------------------------------
__device__ __forceinline__ float2 cmul(float2 a, float2 b){
    return make_float2(fmaf(a.x,b.x,-a.y*b.y), fmaf(a.x,b.y, a.y*b.x));
}
template<bool INV>
__device__ __forceinline__ float2 twid(int t){
    float2 w = g_w224[t];
    if (INV) w.y = -w.y;
    return w;
}
// multiply with b (conjugated when INV)
template<bool INV>
__device__ __forceinline__ float2 cmul_s(float2 a, float2 b){
    float by = INV ? -b.y : b.y;
    return make_float2(fmaf(a.x,b.x,-a.y*by), fmaf(a.x,by, a.y*b.x));
}

// ---- register-cached twiddles (forward sign; INV conjugates at use) --------
template<int LOGG>
struct TW {
    float2 w1, w2, w3;      // DFT-7 roots
    float2 lt[6];           // lane twiddles k=1..6
    float2 st[LOGG];        // shuffle-stage twiddles
    __device__ __forceinline__ void init(int gl){
        w1 = g_w224[32]; w2 = g_w224[64]; w3 = g_w224[96];
        const int ST = 224 / (7 << LOGG);
        #pragma unroll
        for (int k = 1; k < 7; k++) lt[k-1] = g_w224[gl*k*ST];
        int s = 0;
        #pragma unroll
        for (int m = (1 << LOGG)/2; m >= 1; m >>= 1)
            st[s++] = g_w224[(gl & (m-1)) * (224/(2*m))];
    }
};

// ---- core line FFT with register twiddles ----------------------------------
template<int LOGG, bool INV>
__device__ __forceinline__ void fft_regs_t(float2 a[7], int gl, const TW<LOGG>& tw){
    const int G = 1 << LOGG;
    const int N = 7 * G;
    const float sg = INV ? -1.f : 1.f;
    float w1y = sg*tw.w1.y, w2y = sg*tw.w2.y, w3y = sg*tw.w3.y;
    float w1x = tw.w1.x,    w2x = tw.w2.x,    w3x = tw.w3.x;

    float2 a0 = a[0];
    float2 s1 = make_float2(a[1].x+a[6].x, a[1].y+a[6].y);
    float2 s2 = make_float2(a[2].x+a[5].x, a[2].y+a[5].y);
    float2 s3 = make_float2(a[3].x+a[4].x, a[3].y+a[4].y);
    float2 d1 = make_float2(a[1].x-a[6].x, a[1].y-a[6].y);
    float2 d2 = make_float2(a[2].x-a[5].x, a[2].y-a[5].y);
    float2 d3 = make_float2(a[3].x-a[4].x, a[3].y-a[4].y);

    float2 A[7];
    A[0] = make_float2(a0.x + s1.x + s2.x + s3.x,
                       a0.y + s1.y + s2.y + s3.y);
    {
        float px = fmaf(w1x,s1.x, fmaf(w2x,s2.x, fmaf(w3x,s3.x, a0.x)));
        float py = fmaf(w1x,s1.y, fmaf(w2x,s2.y, fmaf(w3x,s3.y, a0.y)));
        float qx = fmaf(w1y,d1.x, fmaf(w2y,d2.x, w3y*d3.x));
        float qy = fmaf(w1y,d1.y, fmaf(w2y,d2.y, w3y*d3.y));
        A[1] = make_float2(px - qy, py + qx);
        A[6] = make_float2(px + qy, py - qx);
    }
    {
        float px = fmaf(w2x,s1.x, fmaf(w3x,s2.x, fmaf(w1x,s3.x, a0.x)));
        float py = fmaf(w2x,s1.y, fmaf(w3x,s2.y, fmaf(w1x,s3.y, a0.y)));
        float qx = fmaf(w2y,d1.x, fmaf(-w3y,d2.x, -w1y*d3.x));
        float qy = fmaf(w2y,d1.y, fmaf(-w3y,d2.y, -w1y*d3.y));
        A[2] = make_float2(px - qy, py + qx);
        A[5] = make_float2(px + qy, py - qx);
    }
    {
        float px = fmaf(w3x,s1.x, fmaf(w1x,s2.x, fmaf(w2x,s3.x, a0.x)));
        float py = fmaf(w3x,s1.y, fmaf(w1x,s2.y, fmaf(w2x,s3.y, a0.y)));
        float qx = fmaf(w3y,d1.x, fmaf(-w1y,d2.x, w2y*d3.x));
        float qy = fmaf(w3y,d1.y, fmaf(-w1y,d2.y, w2y*d3.y));
        A[3] = make_float2(px - qy, py + qx);
        A[4] = make_float2(px + qy, py - qx);
    }

    #pragma unroll
    for (int k1 = 1; k1 < 7; k1++)
        A[k1] = cmul_s<INV>(A[k1], tw.lt[k1-1]);

    int si = 0;
    #pragma unroll
    for (int m = G/2; m >= 1; m >>= 1, si++){
        float2 w = tw.st[si];
        bool up = (gl & m) != 0;
        #pragma unroll
        for (int k1 = 0; k1 < 7; k1++){
            float2 mine = A[k1];
            float2 oth;
            oth.x = __shfl_xor_sync(0xffffffffu, mine.x, m, 32);
            oth.y = __shfl_xor_sync(0xffffffffu, mine.y, m, 32);
            if (up) A[k1] = cmul_s<INV>(make_float2(oth.x - mine.x, oth.y - mine.y), w);
            else    A[k1] = make_float2(mine.x + oth.x, mine.y + oth.y);
        }
    }
    if (INV){
        const float s = 1.0f / (float)N;
        #pragma unroll
        for (int k1 = 0; k1 < 7; k1++){ A[k1].x *= s; A[k1].y *= s; }
    }
    #pragma unroll
    for (int k1 = 0; k1 < 7; k1++) a[k1] = A[k1];
}

// ---- legacy line FFT (global-table twiddles) for the pass kernels ----------
template<int LOGG, bool INV>
__device__ __forceinline__ void fft_regs(float2 a[7], int gl){
    const int G  = 1 << LOGG;
    const int N  = 7 * G;
    const int ST = 224 / N;

    float2 w1 = twid<INV>(32), w2 = twid<INV>(64), w3 = twid<INV>(96);
    float2 a0 = a[0];
    float2 s1 = make_float2(a[1].x+a[6].x, a[1].y+a[6].y);
    float2 s2 = make_float2(a[2].x+a[5].x, a[2].y+a[5].y);
    float2 s3 = make_float2(a[3].x+a[4].x, a[3].y+a[4].y);
    float2 d1 = make_float2(a[1].x-a[6].x, a[1].y-a[6].y);
    float2 d2 = make_float2(a[2].x-a[5].x, a[2].y-a[5].y);
    float2 d3 = make_float2(a[3].x-a[4].x, a[3].y-a[4].y);

    float2 A[7];
    A[0] = make_float2(a0.x + s1.x + s2.x + s3.x,
                       a0.y + s1.y + s2.y + s3.y);
    {
        float px = fmaf(w1.x,s1.x, fmaf(w2.x,s2.x, fmaf(w3.x,s3.x, a0.x)));
        float py = fmaf(w1.x,s1.y, fmaf(w2.x,s2.y, fmaf(w3.x,s3.y, a0.y)));
        float qx = fmaf(w1.y,d1.x, fmaf(w2.y,d2.x, w3.y*d3.x));
        float qy = fmaf(w1.y,d1.y, fmaf(w2.y,d2.y, w3.y*d3.y));
        A[1] = make_float2(px - qy, py + qx);
        A[6] = make_float2(px + qy, py - qx);
    }
    {
        float px = fmaf(w2.x,s1.x, fmaf(w3.x,s2.x, fmaf(w1.x,s3.x, a0.x)));
        float py = fmaf(w2.x,s1.y, fmaf(w3.x,s2.y, fmaf(w1.x,s3.y, a0.y)));
        float qx = fmaf(w2.y,d1.x, fmaf(-w3.y,d2.x, -w1.y*d3.x));
        float qy = fmaf(w2.y,d1.y, fmaf(-w3.y,d2.y, -w1.y*d3.y));
        A[2] = make_float2(px - qy, py + qx);
        A[5] = make_float2(px + qy, py - qx);
    }
    {
        float px = fmaf(w3.x,s1.x, fmaf(w1.x,s2.x, fmaf(w2.x,s3.x, a0.x)));
        float py = fmaf(w3.x,s1.y, fmaf(w1.x,s2.y, fmaf(w2.x,s3.y, a0.y)));
        float qx = fmaf(w3.y,d1.x, fmaf(-w1.y,d2.x, w2.y*d3.x));
        float qy = fmaf(w3.y,d1.y, fmaf(-w1.y,d2.y, w2.y*d3.y));
        A[3] = make_float2(px - qy, py + qx);
        A[4] = make_float2(px + qy, py - qx);
    }

    #pragma unroll
    for (int k1 = 1; k1 < 7; k1++)
        A[k1] = cmul(A[k1], twid<INV>(gl * k1 * ST));

    #pragma unroll
    for (int m = G/2; m >= 1; m >>= 1){
        const int tstep = 224 / (2*m);
        float2 w = twid<INV>((gl & (m-1)) * tstep);
        bool up = (gl & m) != 0;
        #pragma unroll
        for (int k1 = 0; k1 < 7; k1++){
            float2 mine = A[k1];
            float2 oth;
            oth.x = __shfl_xor_sync(0xffffffffu, mine.x, m, 32);
            oth.y = __shfl_xor_sync(0xffffffffu, mine.y, m, 32);
            if (up) A[k1] = cmul(make_float2(oth.x - mine.x, oth.y - mine.y), w);
            else    A[k1] = make_float2(mine.x + oth.x, mine.y + oth.y);
        }
    }
    if (INV){
        const float s = 1.0f / (float)N;
        #pragma unroll
        for (int k1 = 0; k1 < 7; k1++){ A[k1].x *= s; A[k1].y *= s; }
    }
    #pragma unroll
    for (int k1 = 0; k1 < 7; k1++) a[k1] = A[k1];
}

__device__ __forceinline__ float blockMax448(float v){
    #pragma unroll
    for (int o = 16; o; o >>= 1) v = fmaxf(v, __shfl_xor_sync(0xffffffffu, v, o));
    __shared__ float red[14];
    int w = threadIdx.x >> 5;
    if ((threadIdx.x & 31) == 0) red[w] = v;
    __syncthreads();
    float m = -FLT_MAX;
    if (threadIdx.x == 0){
        #pragma unroll
        for (int i = 0; i < 14; i++) m = fmaxf(m, red[i]);
    }
    return m;
}

// ---- filter + twiddle + tap generation (every call) ------------------------
__device__ __forceinline__ float ffreq(int a){
    const float PI = 3.14159265358979f;
    return 2.0f*PI*(float)((a < 112) ? a : a - 224) / 224.0f;
}
__global__ void gen_filters_k(){
    int t = blockIdx.x*256 + threadIdx.x;
    const float PI = 3.14159265358979f;
    if (t < 224){
        double ang = -2.0*3.14159265358979323846*(double)t/224.0;
        g_w224[t] = make_float2((float)cos(ang), (float)sin(ang));
        return;
    }
    int u = t - 224;
    if (u < 2*8*IMG224){
        int j = u / (8*IMG224); int r = u - j*(8*IMG224);
        int l = r / IMG224;     int e = r - l*IMG224;
        int aa = e / 224, bb = e - aa*224;
        float wx = ffreq(aa), wy = ffreq(bb);
        float th = (float)l * (PI / 8.0f);
        float xi = (3.0f*PI/4.0f) / (float)(1 << j);
        float sg = 0.8f * (float)(1 << j);
        float ct = cosf(th), st = sinf(th);
        float uu =  ct*wx + st*wy;
        float vv = -st*wx + ct*wy;
        float vs = vv * 2.0f;                // / slant(=0.5)
        float s2 = 0.5f*sg*sg;
        float gab = expf(-s2*((uu-xi)*(uu-xi) + vs*vs));
        float gau = expf(-s2*(uu*uu + vs*vs));
        float kap = expf(-s2*xi*xi);
        float val = gab - kap*gau;
        if (j == 0) g_psi0[l*IMG224 + e] = val;
        else        g_psi1[l*IMG224 + e] = val;
        return;
    }
    u -= 2*8*IMG224;
    if (u < 32){
        int n, stride;
        if (u < 21){ n = u - 10; stride = 1; }              // g_h0 (224 grid)
        else       { n = u - 21 - 5; stride = 2; }          // g_h1 = h0 at even offsets
        float s = 0.f;
        for (int k = 0; k < 224; k++){
            float w = ffreq(k);
            float ang = 2.0f*PI*(float)(k*n*stride)/224.0f;
            s += expf(-1.28f*w*w) * cosf(ang);
        }
        s /= 224.0f;
        if (u < 21) g_h0[u] = s;
        else        g_h1[u-21] = s;
    }
}

// ---- @224 pass: 16 rows/block (512 thr), row FFT + coalesced transposed write
template<int MODE>
__global__ void __launch_bounds__(512) pass224_k(const float* __restrict__ xin){
    constexpr bool IN_REAL  = (MODE == 0);
    constexpr bool MUL_FILT = (MODE == 2);
    constexpr bool INV      = (MODE == 2 || MODE == 3);

    __shared__ float2 sbuf[16][225];
    int i    = blockIdx.y;
    int w    = threadIdx.x >> 5, lane = threadIdx.x & 31;
    int row  = blockIdx.x*16 + w;

    const float* inR = nullptr; const float2* inC = nullptr; const float* filt = nullptr;
    float2* outp = nullptr;
    if constexpr (MODE == 0){ inR = xin + (size_t)i*IMG224;            outp = g_s1buf; }
    if constexpr (MODE == 1){ inC = g_s1buf + (size_t)i*IMG224;        outp = g_xh;    }
    if constexpr (MODE == 2){ inC = g_xh + (size_t)(i >> 3)*IMG224;
                              filt = g_psi0 + (size_t)(i & 7)*IMG224;  outp = g_s1buf; }
    if constexpr (MODE == 3){ inC = g_s1buf + (size_t)i*IMG224;        outp = g_s2buf; }

    float2 a[7];
    #pragma unroll
    for (int n1 = 0; n1 < 7; n1++){
        int idx = row*224 + n1*32 + lane;
        float2 v;
        if constexpr (IN_REAL) v = make_float2(inR[idx], 0.f);
        else                   v = inC[idx];
        if constexpr (MUL_FILT){ float f = filt[idx]; v.x *= f; v.y *= f; }
        a[n1] = v;
    }
    fft_regs<5, INV>(a, lane);

    if constexpr (MODE == 3){
        // modulus (ifft2 complete) -> save spatial u1 -> forward FFT
        float* rb = (float*)&sbuf[w][0];
        int k2m = __brev((unsigned)lane) >> 27;
        #pragma unroll
        for (int k1 = 0; k1 < 7; k1++)
            rb[k1 + 7*k2m] = sqrtf(a[k1].x*a[k1].x + a[k1].y*a[k1].y);
        __syncwarp();
        float* u1o = g_u1 + (size_t)i*IMG224 + row*224;
        #pragma unroll
        for (int n1 = 0; n1 < 7; n1++){
            float v = rb[n1*32 + lane];
            u1o[n1*32 + lane] = v;
            a[n1] = make_float2(v, 0.f);
        }
        __syncwarp();
        fft_regs<5, false>(a, lane);
    }

    int k2 = __brev((unsigned)lane) >> 27;
    #pragma unroll
    for (int k1 = 0; k1 < 7; k1++) sbuf[w][k1 + 7*k2] = a[k1];
    __syncthreads();

    int rr   = threadIdx.x & 15;
    int kk   = threadIdx.x >> 4;
    int grow = blockIdx.x*16 + rr;
    float2* o = outp + (size_t)i*IMG224;
    #pragma unroll
    for (int it = 0; it < 7; it++){
        int k = kk + it*32;
        o[k*224 + grow] = sbuf[rr][k];
    }
}

// ---- merged pass4 + second-order fold (coalesced) --------------------------
__global__ void __launch_bounds__(512) pass4fold_k(){
    __shared__ float2 sbuf[16][225];
    int i    = blockIdx.y;
    int w    = threadIdx.x >> 5, lane = threadIdx.x & 31;
    int r0   = blockIdx.x * 8;
    int row  = (w < 8) ? (r0 + w) : (r0 + 112 + (w - 8));

    const float2* inC = g_s2buf + (size_t)i*IMG224;
    float2 a[7];
    #pragma unroll
    for (int n1 = 0; n1 < 7; n1++) a[n1] = inC[row*224 + n1*32 + lane];
    fft_regs<5, false>(a, lane);
    int k2 = __brev((unsigned)lane) >> 27;
    #pragma unroll
    for (int k1 = 0; k1 < 7; k1++) sbuf[w][k1 + 7*k2] = a[k1];
    __syncthreads();

    int outBase = 384 + i*8;
    for (int e = threadIdx.x; e < 896; e += 512){
        int aa = e % 112, bbl = e / 112;
        int b = r0 + bbl;
        float2 z00 = sbuf[bbl    ][aa      ];
        float2 z01 = sbuf[bbl    ][aa + 112];
        float2 z10 = sbuf[bbl + 8][aa      ];
        float2 z11 = sbuf[bbl + 8][aa + 112];
        int f00 =  b       *224 + aa;
        int f10 = (b + 112)*224 + aa;
        #pragma unroll
        for (int l2 = 0; l2 < 8; l2++){
            const float* f = g_psi1 + (size_t)l2*IMG224;
            float v00 = f[f00], v01 = f[f00 + 112], v10 = f[f10], v11 = f[f10 + 112];
            float ax = fmaf(z00.x,v00, fmaf(z01.x,v01, fmaf(z10.x,v10, z11.x*v11)));
            float ay = fmaf(z00.y,v00, fmaf(z01.y,v01, fmaf(z10.y,v10, z11.y*v11)));
            g_foldh[(size_t)(outBase + l2)*IMG112 + b*112 + aa] =
                __floats2half2_rn(ax*0.25f, ay*0.25f);
        }
    }
}

// ---- first-order fold (48 xh sources, all 8 l's) ---------------------------
__global__ void __launch_bounds__(512) fold2_k(){
    int s = blockIdx.y;                     // 0..47
    const float2* src = g_xh + (size_t)s*IMG224;
    int outBase = s*8;
    int base = blockIdx.x*1792;
    for (int e = base + threadIdx.x; e < base + 1792; e += 512){
        int aa = e/112, bb = e - aa*112;
        int i00 =  aa      *224 + bb, i01 =  aa      *224 + bb + 112;
        int i10 = (aa+112) *224 + bb, i11 = (aa+112) *224 + bb + 112;
        float2 s00 = src[i00], s01 = src[i01], s10 = src[i10], s11 = src[i11];
        #pragma unroll
        for (int l2 = 0; l2 < 8; l2++){
            const float* f = g_psi1 + (size_t)l2*IMG224;
            float f00 = f[i00], f01 = f[i01], f10 = f[i10], f11 = f[i11];
            float ax = fmaf(s00.x,f00, fmaf(s01.x,f01, fmaf(s10.x,f10, s11.x*f11)));
            float ay = fmaf(s00.y,f00, fmaf(s01.y,f01, fmaf(s10.y,f10, s11.y*f11)));
            g_foldh[(size_t)(outBase + l2)*IMG112 + e] =
                __floats2half2_rn(ax*0.25f, ay*0.25f);
        }
    }
}

// ---- fused @112 chain (fp32 smem, reg-cached twiddles) ---------------------
__device__ __forceinline__ void chain112(const __half2* __restrict__ fsrc,
                                         float* featOut){
    extern __shared__ float2 sm[];
    float2* img = sm;                   // 112 x 113 complex
    float*  smf = (float*)sm;           // float view
    __shared__ float sh_h[11];
    int tid = threadIdx.x;
    if (tid < 11) sh_h[tid] = g_h1[tid];
    int gl = tid & 15, grp = tid >> 4;  // 28 groups of 16

    TW<4> tw; tw.init(gl);              // one twiddle load set, reused 8x

    // ifft2 row pass, loading straight from global (fp16 -> fp32)
    for (int r = grp; r < 112; r += 28){
        float2 a[7];
        #pragma unroll
        for (int n1 = 0; n1 < 7; n1++)
            a[n1] = __half22float2(fsrc[r*112 + n1*16 + gl]);
        fft_regs_t<4, true>(a, gl, tw);
        int k2 = __brev((unsigned)gl) >> 28;
        #pragma unroll
        for (int k1 = 0; k1 < 7; k1++) img[r*113 + k1 + 7*k2] = a[k1];
    }
    __syncthreads();
    // ifft2 col pass, modulus stored into .x slots
    for (int c = grp; c < 112; c += 28){
        float2 a[7];
        #pragma unroll
        for (int n1 = 0; n1 < 7; n1++) a[n1] = img[(n1*16 + gl)*113 + c];
        fft_regs_t<4, true>(a, gl, tw);
        int k2 = __brev((unsigned)gl) >> 28;
        #pragma unroll
        for (int k1 = 0; k1 < 7; k1++){
            float2 z = a[k1];
            smf[((k1 + 7*k2)*113 + c)*2] = sqrtf(z.x*z.x + z.y*z.y);
        }
    }
    __syncthreads();

    // horizontal blur at stride-2 output columns: hb[r][c] (112 x 56)
    float rh[14];
    #pragma unroll
    for (int it = 0; it < 14; it++){
        int e = tid + it*448;
        int r = e % 112, c = e / 112;
        float acc = 0.f;
        #pragma unroll
        for (int d = 0; d < 11; d++){
            int cc = 2*c + d - 5;
            if (cc < 0) cc += 112; else if (cc >= 112) cc -= 112;
            acc = fmaf(sh_h[d], smf[(r*113 + cc)*2], acc);
        }
        rh[it] = acc;
    }
    __syncthreads();
    #pragma unroll
    for (int it = 0; it < 14; it++){
        int e = tid + it*448;
        int r = e % 112, c = e / 112;
        smf[r*57 + c] = rh[it];          // hb overlay, pitch 57
    }
    __syncthreads();

    // vertical blur at stride-2 output rows + max
    float mx = -FLT_MAX;
    #pragma unroll
    for (int it = 0; it < 7; it++){
        int e = tid + it*448;
        int a = e / 56, b = e % 56;
        float acc = 0.f;
        #pragma unroll
        for (int d = 0; d < 11; d++){
            int rr = 2*a + d - 5;
            if (rr < 0) rr += 112; else if (rr >= 112) rr -= 112;
            acc = fmaf(sh_h[d], smf[rr*57 + b], acc);
        }
        mx = fmaxf(mx, acc);
    }
    float m = blockMax448(mx);
    if (tid == 0) *featOut = m;
}

// merged j1=1 first order + second order (3456 blocks)
__global__ void __launch_bounds__(448, 2) scatter2_k(){
    int i = blockIdx.x;
    int featIdx;
    if (i < 384){
        int bc = i >> 3, l = i & 7;
        featIdx = bc*81 + 9 + l;
    } else {
        int v = i - 384;
        int bc = v >> 6, l1 = (v >> 3) & 7, l2 = v & 7;
        featIdx = bc*81 + 17 + l1*8 + l2;
    }
    chain112(g_foldh + (size_t)i*IMG112, &g_feat[featIdx]);
}

// ---- s0 / s1(j1=0): spatial blur @224, stride 4, circular, + max -----------
__global__ void __launch_bounds__(448) blur224_k(const float* __restrict__ x){
    __shared__ float hb[224*57];        // 51KB
    __shared__ float sh_h[21];
    int i = blockIdx.x;                 // [0,48): s0 from x ; [48,432): s1 j1=0 from u1
    const float* src; int featIdx;
    if (i < 48){ src = x + (size_t)i*IMG224; featIdx = i*81; }
    else {
        int j = i - 48;
        src = g_u1 + (size_t)j*IMG224;
        featIdx = (j >> 3)*81 + 1 + (j & 7);
    }
    int tid = threadIdx.x;
    if (tid < 21) sh_h[tid] = g_h0[tid];
    __syncthreads();

    int rr = tid / 56, c = tid % 56;    // 8 rows x 56 cols per sweep
    for (int r0 = 0; r0 < 224; r0 += 8){
        int r = r0 + rr;
        float acc = 0.f;
        #pragma unroll
        for (int d = 0; d < 21; d++){
            int cc = 4*c + d - 10;
            if (cc < 0) cc += 224; else if (cc >= 224) cc -= 224;
            acc = fmaf(sh_h[d], __ldg(src + r*224 + cc), acc);
        }
        hb[r*57 + c] = acc;
    }
    __syncthreads();

    float mx = -FLT_MAX;
    #pragma unroll
    for (int it = 0; it < 7; it++){
        int e = tid + it*448;
        int a = e / 56, b = e % 56;
        float acc = 0.f;
        #pragma unroll
        for (int d = 0; d < 21; d++){
            int r2 = 4*a + d - 10;
            if (r2 < 0) r2 += 224; else if (r2 >= 224) r2 -= 224;
            acc = fmaf(sh_h[d], hb[r2*57 + b], acc);
        }
        mx = fmaxf(mx, acc);
    }
    float m = blockMax448(mx);
    if (tid == 0) g_feat[featIdx] = m;
}

// ---- final linear ----------------------------------------------------------
__global__ void linear_k(const float* __restrict__ W, const float* __restrict__ bias,
                         float* __restrict__ out){
    __shared__ float gs[243];
    int b = blockIdx.x;
    for (int k = threadIdx.x; k < 243; k += 256) gs[k] = g_feat[b*243 + k];
    __syncthreads();
    for (int o = threadIdx.x; o < 1000; o += 256){
        float acc = bias[o];
        const float* wr = W + o*243;
        #pragma unroll 3
        for (int k = 0; k < 243; k++) acc = fmaf(gs[k], wr[k], acc);
        out[b*1000 + o] = acc;
    }
}

// ---------------------------------------------------------------------------
extern "C" void kernel_launch(void* const* d_in, const int* in_sizes, int n_in,
                              void* d_out, int out_size){
    const float *x = nullptr, *W = nullptr, *bias = nullptr;
    for (int i = 0; i < n_in; i++){
        if      (in_sizes[i] == 16*3*224*224) x    = (const float*)d_in[i];
        else if (in_sizes[i] == 1000*243)     W    = (const float*)d_in[i];
        else if (in_sizes[i] == 1000)         bias = (const float*)d_in[i];
    }
    float* out = (float*)d_out;

    const int SM_CHAIN = 112*113*(int)sizeof(float2);  // 101,248 B
    cudaFuncSetAttribute(scatter2_k, cudaFuncAttributeMaxDynamicSharedMemorySize, SM_CHAIN);

    int genTotal = 224 + 2*8*IMG224 + 32;
    gen_filters_k<<<(genTotal + 255)/256, 256>>>();

    pass224_k<0><<<dim3(14, 48),  512>>>(x);        // x -> s1buf (rows fwd)
    pass224_k<1><<<dim3(14, 48),  512>>>(nullptr);  // s1buf -> xh
    pass224_k<2><<<dim3(14, 384), 512>>>(nullptr);  // xh*psi0 -> s1buf (inv)
    pass224_k<3><<<dim3(14, 384), 512>>>(nullptr);  // inv + |.| -> u1, fwd -> s2buf

    pass4fold_k<<<dim3(14, 384), 512>>>();          // col FFT + fold*psi1 -> g_foldh
    fold2_k<<<dim3(7, 48), 512>>>();                // first-order folds -> g_foldh
    blur224_k<<<432, 448>>>(x);                     // s0 + s1(j1=0) via spatial blur
    scatter2_k<<<3456, 448, SM_CHAIN>>>();          // s1(j1=1) + s2
    linear_k<<<16, 256>>>(W, bias, out);
    (void)out_size;
}

// round 11
// speedup vs baseline: 1.0874x; 1.0185x over previous
#include <cuda_runtime.h>
#include <cuda_fp16.h>
#include <math.h>
#include <float.h>

// ---------------------------------------------------------------------------
// Scattering2D (J=2, L=8, 224x224) B=16, C=3  + global max pool + linear.
// FFTs: symmetric-pair 7-point DFT per lane x radix-2 shuffle FFT across lanes.
// Low-pass (phi) stages are exact spatial separable Gaussian blurs.
// Second-order fold fused into the final 224-pass (coalesced); fold in fp16.
// Chain: SoA fp32 smem (odd pitch 115 -> conflict-free), reg-cached twiddles.
// ---------------------------------------------------------------------------

#define IMG224 (224*224)
#define IMG112 (112*112)
#define CPITCH 115                       // chain smem pitch (odd mod 32)

// ---- device global scratch -------------------------------------------------
__device__ float2  g_w224[224];
__device__ float   g_psi0[8*IMG224];     // j=0 Morlets @224
__device__ float   g_psi1[8*IMG224];     // j=1 Morlets @224
__device__ float   g_h0[21];             // spatial phi taps @224 (stride-4 path)
__device__ float   g_h1[11];             // spatial phi taps @112 (stride-2 path)
__device__ float2  g_xh[48*IMG224];      // fft2(x)
__device__ float2  g_s1buf[384*IMG224];  // scratch A
__device__ float2  g_s2buf[384*IMG224];  // scratch B
__device__ __half  g_u1h[384*IMG224];    // spatial u1 [TRANSPOSED layout] fp16
__device__ __half2 g_foldh[3456*IMG112]; // prefolded 112x112 chain inputs (fp16)
__device__ float   g_feat[48*81];        // scattering features

// ---- complex helpers -------------------------------------------------------
__device__ __forceinline__ float2 cmul(float2 a, float2 b){
    return make_float2(fmaf(a.x,b.x,-a.y*b.y), fmaf(a.x,b.y, a.y*b.x));
}
template<bool INV>
__device__ __forceinline__ float2 twid(int t){
    float2 w = g_w224[t];
    if (INV) w.y = -w.y;
    return w;
}
template<bool INV>
__device__ __forceinline__ float2 cmul_s(float2 a, float2 b){
    float by = INV ? -b.y : b.y;
    return make_float2(fmaf(a.x,b.x,-a.y*by), fmaf(a.x,by, a.y*b.x));
}

// ---- register-cached twiddles (forward sign; INV conjugates at use) --------
template<int LOGG>
struct TW {
    float2 w1, w2, w3;      // DFT-7 roots
    float2 lt[6];           // lane twiddles k=1..6
    float2 st[LOGG];        // shuffle-stage twiddles
    __device__ __forceinline__ void init(int gl){
        w1 = g_w224[32]; w2 = g_w224[64]; w3 = g_w224[96];
        const int ST = 224 / (7 << LOGG);
        #pragma unroll
        for (int k = 1; k < 7; k++) lt[k-1] = g_w224[gl*k*ST];
        int s = 0;
        #pragma unroll
        for (int m = (1 << LOGG)/2; m >= 1; m >>= 1)
            st[s++] = g_w224[(gl & (m-1)) * (224/(2*m))];
    }
};

// ---- core line FFT with register twiddles ----------------------------------
template<int LOGG, bool INV>
__device__ __forceinline__ void fft_regs_t(float2 a[7], int gl, const TW<LOGG>& tw){
    const int G = 1 << LOGG;
    const int N = 7 * G;
    const float sg = INV ? -1.f : 1.f;
    float w1y = sg*tw.w1.y, w2y = sg*tw.w2.y, w3y = sg*tw.w3.y;
    float w1x = tw.w1.x,    w2x = tw.w2.x,    w3x = tw.w3.x;

    float2 a0 = a[0];
    float2 s1 = make_float2(a[1].x+a[6].x, a[1].y+a[6].y);
    float2 s2 = make_float2(a[2].x+a[5].x, a[2].y+a[5].y);
    float2 s3 = make_float2(a[3].x+a[4].x, a[3].y+a[4].y);
    float2 d1 = make_float2(a[1].x-a[6].x, a[1].y-a[6].y);
    float2 d2 = make_float2(a[2].x-a[5].x, a[2].y-a[5].y);
    float2 d3 = make_float2(a[3].x-a[4].x, a[3].y-a[4].y);

    float2 A[7];
    A[0] = make_float2(a0.x + s1.x + s2.x + s3.x,
                       a0.y + s1.y + s2.y + s3.y);
    {
        float px = fmaf(w1x,s1.x, fmaf(w2x,s2.x, fmaf(w3x,s3.x, a0.x)));
        float py = fmaf(w1x,s1.y, fmaf(w2x,s2.y, fmaf(w3x,s3.y, a0.y)));
        float qx = fmaf(w1y,d1.x, fmaf(w2y,d2.x, w3y*d3.x));
        float qy = fmaf(w1y,d1.y, fmaf(w2y,d2.y, w3y*d3.y));
        A[1] = make_float2(px - qy, py + qx);
        A[6] = make_float2(px + qy, py - qx);
    }
    {
        float px = fmaf(w2x,s1.x, fmaf(w3x,s2.x, fmaf(w1x,s3.x, a0.x)));
        float py = fmaf(w2x,s1.y, fmaf(w3x,s2.y, fmaf(w1x,s3.y, a0.y)));
        float qx = fmaf(w2y,d1.x, fmaf(-w3y,d2.x, -w1y*d3.x));
        float qy = fmaf(w2y,d1.y, fmaf(-w3y,d2.y, -w1y*d3.y));
        A[2] = make_float2(px - qy, py + qx);
        A[5] = make_float2(px + qy, py - qx);
    }
    {
        float px = fmaf(w3x,s1.x, fmaf(w1x,s2.x, fmaf(w2x,s3.x, a0.x)));
        float py = fmaf(w3x,s1.y, fmaf(w1x,s2.y, fmaf(w2x,s3.y, a0.y)));
        float qx = fmaf(w3y,d1.x, fmaf(-w1y,d2.x, w2y*d3.x));
        float qy = fmaf(w3y,d1.y, fmaf(-w1y,d2.y, w2y*d3.y));
        A[3] = make_float2(px - qy, py + qx);
        A[4] = make_float2(px + qy, py - qx);
    }

    #pragma unroll
    for (int k1 = 1; k1 < 7; k1++)
        A[k1] = cmul_s<INV>(A[k1], tw.lt[k1-1]);

    int si = 0;
    #pragma unroll
    for (int m = G/2; m >= 1; m >>= 1, si++){
        float2 w = tw.st[si];
        bool up = (gl & m) != 0;
        #pragma unroll
        for (int k1 = 0; k1 < 7; k1++){
            float2 mine = A[k1];
            float2 oth;
            oth.x = __shfl_xor_sync(0xffffffffu, mine.x, m, 32);
            oth.y = __shfl_xor_sync(0xffffffffu, mine.y, m, 32);
            if (up) A[k1] = cmul_s<INV>(make_float2(oth.x - mine.x, oth.y - mine.y), w);
            else    A[k1] = make_float2(mine.x + oth.x, mine.y + oth.y);
        }
    }
    if (INV){
        const float s = 1.0f / (float)N;
        #pragma unroll
        for (int k1 = 0; k1 < 7; k1++){ A[k1].x *= s; A[k1].y *= s; }
    }
    #pragma unroll
    for (int k1 = 0; k1 < 7; k1++) a[k1] = A[k1];
}

// ---- legacy line FFT (global-table twiddles) for the pass kernels ----------
template<int LOGG, bool INV>
__device__ __forceinline__ void fft_regs(float2 a[7], int gl){
    const int G  = 1 << LOGG;
    const int N  = 7 * G;
    const int ST = 224 / N;

    float2 w1 = twid<INV>(32), w2 = twid<INV>(64), w3 = twid<INV>(96);
    float2 a0 = a[0];
    float2 s1 = make_float2(a[1].x+a[6].x, a[1].y+a[6].y);
    float2 s2 = make_float2(a[2].x+a[5].x, a[2].y+a[5].y);
    float2 s3 = make_float2(a[3].x+a[4].x, a[3].y+a[4].y);
    float2 d1 = make_float2(a[1].x-a[6].x, a[1].y-a[6].y);
    float2 d2 = make_float2(a[2].x-a[5].x, a[2].y-a[5].y);
    float2 d3 = make_float2(a[3].x-a[4].x, a[3].y-a[4].y);

    float2 A[7];
    A[0] = make_float2(a0.x + s1.x + s2.x + s3.x,
                       a0.y + s1.y + s2.y + s3.y);
    {
        float px = fmaf(w1.x,s1.x, fmaf(w2.x,s2.x, fmaf(w3.x,s3.x, a0.x)));
        float py = fmaf(w1.x,s1.y, fmaf(w2.x,s2.y, fmaf(w3.x,s3.y, a0.y)));
        float qx = fmaf(w1.y,d1.x, fmaf(w2.y,d2.x, w3.y*d3.x));
        float qy = fmaf(w1.y,d1.y, fmaf(w2.y,d2.y, w3.y*d3.y));
        A[1] = make_float2(px - qy, py + qx);
        A[6] = make_float2(px + qy, py - qx);
    }
    {
        float px = fmaf(w2.x,s1.x, fmaf(w3.x,s2.x, fmaf(w1.x,s3.x, a0.x)));
        float py = fmaf(w2.x,s1.y, fmaf(w3.x,s2.y, fmaf(w1.x,s3.y, a0.y)));
        float qx = fmaf(w2.y,d1.x, fmaf(-w3.y,d2.x, -w1.y*d3.x));
        float qy = fmaf(w2.y,d1.y, fmaf(-w3.y,d2.y, -w1.y*d3.y));
        A[2] = make_float2(px - qy, py + qx);
        A[5] = make_float2(px + qy, py - qx);
    }
    {
        float px = fmaf(w3.x,s1.x, fmaf(w1.x,s2.x, fmaf(w2.x,s3.x, a0.x)));
        float py = fmaf(w3.x,s1.y, fmaf(w1.x,s2.y, fmaf(w2.x,s3.y, a0.y)));
        float qx = fmaf(w3.y,d1.x, fmaf(-w1.y,d2.x, w2.y*d3.x));
        float qy = fmaf(w3.y,d1.y, fmaf(-w1.y,d2.y, w2.y*d3.y));
        A[3] = make_float2(px - qy, py + qx);
        A[4] = make_float2(px + qy, py - qx);
    }

    #pragma unroll
    for (int k1 = 1; k1 < 7; k1++)
        A[k1] = cmul(A[k1], twid<INV>(gl * k1 * ST));

    #pragma unroll
    for (int m = G/2; m >= 1; m >>= 1){
        const int tstep = 224 / (2*m);
        float2 w = twid<INV>((gl & (m-1)) * tstep);
        bool up = (gl & m) != 0;
        #pragma unroll
        for (int k1 = 0; k1 < 7; k1++){
            float2 mine = A[k1];
            float2 oth;
            oth.x = __shfl_xor_sync(0xffffffffu, mine.x, m, 32);
            oth.y = __shfl_xor_sync(0xffffffffu, mine.y, m, 32);
            if (up) A[k1] = cmul(make_float2(oth.x - mine.x, oth.y - mine.y), w);
            else    A[k1] = make_float2(mine.x + oth.x, mine.y + oth.y);
        }
    }
    if (INV){
        const float s = 1.0f / (float)N;
        #pragma unroll
        for (int k1 = 0; k1 < 7; k1++){ A[k1].x *= s; A[k1].y *= s; }
    }
    #pragma unroll
    for (int k1 = 0; k1 < 7; k1++) a[k1] = A[k1];
}

__device__ __forceinline__ float blockMax448(float v){
    #pragma unroll
    for (int o = 16; o; o >>= 1) v = fmaxf(v, __shfl_xor_sync(0xffffffffu, v, o));
    __shared__ float red[14];
    int w = threadIdx.x >> 5;
    if ((threadIdx.x & 31) == 0) red[w] = v;
    __syncthreads();
    float m = -FLT_MAX;
    if (threadIdx.x == 0){
        #pragma unroll
        for (int i = 0; i < 14; i++) m = fmaxf(m, red[i]);
    }
    return m;
}

// ---- filter + twiddle + tap generation (every call) ------------------------
__device__ __forceinline__ float ffreq(int a){
    const float PI = 3.14159265358979f;
    return 2.0f*PI*(float)((a < 112) ? a : a - 224) / 224.0f;
}
__global__ void gen_filters_k(){
    int t = blockIdx.x*256 + threadIdx.x;
    const float PI = 3.14159265358979f;
    if (t < 224){
        double ang = -2.0*3.14159265358979323846*(double)t/224.0;
        g_w224[t] = make_float2((float)cos(ang), (float)sin(ang));
        return;
    }
    int u = t - 224;
    if (u < 2*8*IMG224){
        int j = u / (8*IMG224); int r = u - j*(8*IMG224);
        int l = r / IMG224;     int e = r - l*IMG224;
        int aa = e / 224, bb = e - aa*224;
        float wx = ffreq(aa), wy = ffreq(bb);
        float th = (float)l * (PI / 8.0f);
        float xi = (3.0f*PI/4.0f) / (float)(1 << j);
        float sg = 0.8f * (float)(1 << j);
        float ct = cosf(th), st = sinf(th);
        float uu =  ct*wx + st*wy;
        float vv = -st*wx + ct*wy;
        float vs = vv * 2.0f;                // / slant(=0.5)
        float s2 = 0.5f*sg*sg;
        float gab = expf(-s2*((uu-xi)*(uu-xi) + vs*vs));
        float gau = expf(-s2*(uu*uu + vs*vs));
        float kap = expf(-s2*xi*xi);
        float val = gab - kap*gau;
        if (j == 0) g_psi0[l*IMG224 + e] = val;
        else        g_psi1[l*IMG224 + e] = val;
        return;
    }
    u -= 2*8*IMG224;
    if (u < 32){
        int n, stride;
        if (u < 21){ n = u - 10; stride = 1; }              // g_h0 (224 grid)
        else       { n = u - 21 - 5; stride = 2; }          // g_h1 = h0 at even offsets
        float s = 0.f;
        for (int k = 0; k < 224; k++){
            float w = ffreq(k);
            float ang = 2.0f*PI*(float)(k*n*stride)/224.0f;
            s += expf(-1.28f*w*w) * cosf(ang);
        }
        s /= 224.0f;
        if (u < 21) g_h0[u] = s;
        else        g_h1[u-21] = s;
    }
}

// ---- @224 pass: 16 rows/block (512 thr), row FFT + coalesced transposed write
template<int MODE>
__global__ void __launch_bounds__(512) pass224_k(const float* __restrict__ xin){
    constexpr bool IN_REAL  = (MODE == 0);
    constexpr bool MUL_FILT = (MODE == 2);
    constexpr bool INV      = (MODE == 2 || MODE == 3);

    __shared__ float2 sbuf[16][225];
    int i    = blockIdx.y;
    int w    = threadIdx.x >> 5, lane = threadIdx.x & 31;
    int row  = blockIdx.x*16 + w;

    const float* inR = nullptr; const float2* inC = nullptr; const float* filt = nullptr;
    float2* outp = nullptr;
    if constexpr (MODE == 0){ inR = xin + (size_t)i*IMG224;            outp = g_s1buf; }
    if constexpr (MODE == 1){ inC = g_s1buf + (size_t)i*IMG224;        outp = g_xh;    }
    if constexpr (MODE == 2){ inC = g_xh + (size_t)(i >> 3)*IMG224;
                              filt = g_psi0 + (size_t)(i & 7)*IMG224;  outp = g_s1buf; }
    if constexpr (MODE == 3){ inC = g_s1buf + (size_t)i*IMG224;        outp = g_s2buf; }

    float2 a[7];
    #pragma unroll
    for (int n1 = 0; n1 < 7; n1++){
        int idx = row*224 + n1*32 + lane;
        float2 v;
        if constexpr (IN_REAL) v = make_float2(inR[idx], 0.f);
        else                   v = inC[idx];
        if constexpr (MUL_FILT){ float f = filt[idx]; v.x *= f; v.y *= f; }
        a[n1] = v;
    }
    fft_regs<5, INV>(a, lane);

    if constexpr (MODE == 3){
        // modulus (ifft2 complete) -> save spatial u1 (fp16) -> forward FFT
        float* rb = (float*)&sbuf[w][0];
        int k2m = __brev((unsigned)lane) >> 27;
        #pragma unroll
        for (int k1 = 0; k1 < 7; k1++)
            rb[k1 + 7*k2m] = sqrtf(a[k1].x*a[k1].x + a[k1].y*a[k1].y);
        __syncwarp();
        __half* u1o = g_u1h + (size_t)i*IMG224 + row*224;
        #pragma unroll
        for (int n1 = 0; n1 < 7; n1++){
            float v = rb[n1*32 + lane];
            u1o[n1*32 + lane] = __float2half(v);
            a[n1] = make_float2(v, 0.f);
        }
        __syncwarp();
        fft_regs<5, false>(a, lane);
    }

    int k2 = __brev((unsigned)lane) >> 27;
    #pragma unroll
    for (int k1 = 0; k1 < 7; k1++) sbuf[w][k1 + 7*k2] = a[k1];
    __syncthreads();

    int rr   = threadIdx.x & 15;
    int kk   = threadIdx.x >> 4;
    int grow = blockIdx.x*16 + rr;
    float2* o = outp + (size_t)i*IMG224;
    #pragma unroll
    for (int it = 0; it < 7; it++){
        int k = kk + it*32;
        o[k*224 + grow] = sbuf[rr][k];
    }
}

// ---- merged pass4 + second-order fold (coalesced) --------------------------
__global__ void __launch_bounds__(512) pass4fold_k(){
    __shared__ float2 sbuf[16][225];
    int i    = blockIdx.y;
    int w    = threadIdx.x >> 5, lane = threadIdx.x & 31;
    int r0   = blockIdx.x * 8;
    int row  = (w < 8) ? (r0 + w) : (r0 + 112 + (w - 8));

    const float2* inC = g_s2buf + (size_t)i*IMG224;
    float2 a[7];
    #pragma unroll
    for (int n1 = 0; n1 < 7; n1++) a[n1] = inC[row*224 + n1*32 + lane];
    fft_regs<5, false>(a, lane);
    int k2 = __brev((unsigned)lane) >> 27;
    #pragma unroll
    for (int k1 = 0; k1 < 7; k1++) sbuf[w][k1 + 7*k2] = a[k1];
    __syncthreads();

    int outBase = 384 + i*8;
    for (int e = threadIdx.x; e < 896; e += 512){
        int aa = e % 112, bbl = e / 112;
        int b = r0 + bbl;
        float2 z00 = sbuf[bbl    ][aa      ];
        float2 z01 = sbuf[bbl    ][aa + 112];
        float2 z10 = sbuf[bbl + 8][aa      ];
        float2 z11 = sbuf[bbl + 8][aa + 112];
        int f00 =  b       *224 + aa;
        int f10 = (b + 112)*224 + aa;
        #pragma unroll
        for (int l2 = 0; l2 < 8; l2++){
            const float* f = g_psi1 + (size_t)l2*IMG224;
            float v00 = f[f00], v01 = f[f00 + 112], v10 = f[f10], v11 = f[f10 + 112];
            float ax = fmaf(z00.x,v00, fmaf(z01.x,v01, fmaf(z10.x,v10, z11.x*v11)));
            float ay = fmaf(z00.y,v00, fmaf(z01.y,v01, fmaf(z10.y,v10, z11.y*v11)));
            g_foldh[(size_t)(outBase + l2)*IMG112 + b*112 + aa] =
                __floats2half2_rn(ax*0.25f, ay*0.25f);
        }
    }
}

// ---- first-order fold (48 xh sources, all 8 l's) ---------------------------
__global__ void __launch_bounds__(512) fold2_k(){
    int s = blockIdx.y;                     // 0..47
    const float2* src = g_xh + (size_t)s*IMG224;
    int outBase = s*8;
    int base = blockIdx.x*1792;
    for (int e = base + threadIdx.x; e < base + 1792; e += 512){
        int aa = e/112, bb = e - aa*112;
        int i00 =  aa      *224 + bb, i01 =  aa      *224 + bb + 112;
        int i10 = (aa+112) *224 + bb, i11 = (aa+112) *224 + bb + 112;
        float2 s00 = src[i00], s01 = src[i01], s10 = src[i10], s11 = src[i11];
        #pragma unroll
        for (int l2 = 0; l2 < 8; l2++){
            const float* f = g_psi1 + (size_t)l2*IMG224;
            float f00 = f[i00], f01 = f[i01], f10 = f[i10], f11 = f[i11];
            float ax = fmaf(s00.x,f00, fmaf(s01.x,f01, fmaf(s10.x,f10, s11.x*f11)));
            float ay = fmaf(s00.y,f00, fmaf(s01.y,f01, fmaf(s10.y,f10, s11.y*f11)));
            g_foldh[(size_t)(outBase + l2)*IMG112 + e] =
                __floats2half2_rn(ax*0.25f, ay*0.25f);
        }
    }
}

// ---- fused @112 chain (SoA fp32 smem, pitch 115, conflict-free) ------------
__device__ __forceinline__ void chain112(const __half2* __restrict__ fsrc,
                                         float* featOut){
    extern __shared__ float smf[];
    float* reS = smf;                    // 112 x 115 floats
    float* imS = smf + 112*CPITCH;       // 112 x 115 floats (dead after col pass)
    __shared__ float sh_h[11];
    int tid = threadIdx.x;
    if (tid < 11) sh_h[tid] = g_h1[tid];
    int gl = tid & 15, grp = tid >> 4;   // 28 groups of 16

    TW<4> tw; tw.init(gl);               // one twiddle load set, reused 8x

    // ifft2 row pass: global (fp16) -> fp32 FFT -> SoA smem
    for (int r = grp; r < 112; r += 28){
        float2 a[7];
        #pragma unroll
        for (int n1 = 0; n1 < 7; n1++)
            a[n1] = __half22float2(fsrc[r*112 + n1*16 + gl]);
        fft_regs_t<4, true>(a, gl, tw);
        int k2 = __brev((unsigned)gl) >> 28;
        #pragma unroll
        for (int k1 = 0; k1 < 7; k1++){
            int p = r*CPITCH + k1 + 7*k2;
            reS[p] = a[k1].x;
            imS[p] = a[k1].y;
        }
    }
    __syncthreads();
    // ifft2 col pass: fp32 FFT, modulus -> reS in place (imS becomes dead)
    for (int c = grp; c < 112; c += 28){
        float2 a[7];
        #pragma unroll
        for (int n1 = 0; n1 < 7; n1++){
            int p = (n1*16 + gl)*CPITCH + c;
            a[n1] = make_float2(reS[p], imS[p]);
        }
        fft_regs_t<4, true>(a, gl, tw);
        int k2 = __brev((unsigned)gl) >> 28;
        #pragma unroll
        for (int k1 = 0; k1 < 7; k1++){
            float2 z = a[k1];
            reS[(k1 + 7*k2)*CPITCH + c] = sqrtf(z.x*z.x + z.y*z.y);
        }
    }
    __syncthreads();

    // horizontal blur at stride-2 output cols; hb lives in dead imS (no alias)
    float* hb = imS;                     // 112 x 57
    #pragma unroll
    for (int it = 0; it < 14; it++){
        int e = tid + it*448;
        int r = e % 112, c = e / 112;
        float acc = 0.f;
        #pragma unroll
        for (int d = 0; d < 11; d++){
            int cc = 2*c + d - 5;
            if (cc < 0) cc += 112; else if (cc >= 112) cc -= 112;
            acc = fmaf(sh_h[d], reS[r*CPITCH + cc], acc);
        }
        hb[r*57 + c] = acc;
    }
    __syncthreads();

    // vertical blur at stride-2 output rows + max
    float mx = -FLT_MAX;
    #pragma unroll
    for (int it = 0; it < 7; it++){
        int e = tid + it*448;
        int a = e / 56, b = e % 56;
        float acc = 0.f;
        #pragma unroll
        for (int d = 0; d < 11; d++){
            int rr = 2*a + d - 5;
            if (rr < 0) rr += 112; else if (rr >= 112) rr -= 112;
            acc = fmaf(sh_h[d], hb[rr*57 + b], acc);
        }
        mx = fmaxf(mx, acc);
    }
    float m = blockMax448(mx);
    if (tid == 0) *featOut = m;
}

// merged j1=1 first order + second order (3456 blocks)
__global__ void __launch_bounds__(448, 2) scatter2_k(){
    int i = blockIdx.x;
    int featIdx;
    if (i < 384){
        int bc = i >> 3, l = i & 7;
        featIdx = bc*81 + 9 + l;
    } else {
        int v = i - 384;
        int bc = v >> 6, l1 = (v >> 3) & 7, l2 = v & 7;
        featIdx = bc*81 + 17 + l1*8 + l2;
    }
    chain112(g_foldh + (size_t)i*IMG112, &g_feat[featIdx]);
}

// ---- s0 / s1(j1=0): spatial blur @224, stride 4, circular, + max -----------
__global__ void __launch_bounds__(448) blur224_k(const float* __restrict__ x){
    __shared__ float hb[224*57];        // 51KB
    __shared__ float sh_h[21];
    int i = blockIdx.x;                 // [0,48): s0 from x ; [48,432): s1 j1=0 from u1
    const float* srcF = nullptr; const __half* srcH = nullptr; int featIdx;
    if (i < 48){ srcF = x + (size_t)i*IMG224; featIdx = i*81; }
    else {
        int j = i - 48;
        srcH = g_u1h + (size_t)j*IMG224;
        featIdx = (j >> 3)*81 + 1 + (j & 7);
    }
    int tid = threadIdx.x;
    if (tid < 21) sh_h[tid] = g_h0[tid];
    __syncthreads();

    int rr = tid / 56, c = tid % 56;    // 8 rows x 56 cols per sweep
    for (int r0 = 0; r0 < 224; r0 += 8){
        int r = r0 + rr;
        float acc = 0.f;
        #pragma unroll
        for (int d = 0; d < 21; d++){
            int cc = 4*c + d - 10;
            if (cc < 0) cc += 224; else if (cc >= 224) cc -= 224;
            float v = srcF ? __ldg(srcF + r*224 + cc)
                           : __half2float(srcH[r*224 + cc]);
            acc = fmaf(sh_h[d], v, acc);
        }
        hb[r*57 + c] = acc;
    }
    __syncthreads();

    float mx = -FLT_MAX;
    #pragma unroll
    for (int it = 0; it < 7; it++){
        int e = tid + it*448;
        int a = e / 56, b = e % 56;
        float acc = 0.f;
        #pragma unroll
        for (int d = 0; d < 21; d++){
            int r2 = 4*a + d - 10;
            if (r2 < 0) r2 += 224; else if (r2 >= 224) r2 -= 224;
            acc = fmaf(sh_h[d], hb[r2*57 + b], acc);
        }
        mx = fmaxf(mx, acc);
    }
    float m = blockMax448(mx);
    if (tid == 0) g_feat[featIdx] = m;
}

// ---- final linear ----------------------------------------------------------
__global__ void linear_k(const float* __restrict__ W, const float* __restrict__ bias,
                         float* __restrict__ out){
    __shared__ float gs[243];
    int b = blockIdx.x;
    for (int k = threadIdx.x; k < 243; k += 256) gs[k] = g_feat[b*243 + k];
    __syncthreads();
    for (int o = threadIdx.x; o < 1000; o += 256){
        float acc = bias[o];
        const float* wr = W + o*243;
        #pragma unroll 3
        for (int k = 0; k < 243; k++) acc = fmaf(gs[k], wr[k], acc);
        out[b*1000 + o] = acc;
    }
}

// ---------------------------------------------------------------------------
extern "C" void kernel_launch(void* const* d_in, const int* in_sizes, int n_in,
                              void* d_out, int out_size){
    const float *x = nullptr, *W = nullptr, *bias = nullptr;
    for (int i = 0; i < n_in; i++){
        if      (in_sizes[i] == 16*3*224*224) x    = (const float*)d_in[i];
        else if (in_sizes[i] == 1000*243)     W    = (const float*)d_in[i];
        else if (in_sizes[i] == 1000)         bias = (const float*)d_in[i];
    }
    float* out = (float*)d_out;

    const int SM_CHAIN = 2*112*CPITCH*(int)sizeof(float);  // 103,040 B
    cudaFuncSetAttribute(scatter2_k, cudaFuncAttributeMaxDynamicSharedMemorySize, SM_CHAIN);

    int genTotal = 224 + 2*8*IMG224 + 32;
    gen_filters_k<<<(genTotal + 255)/256, 256>>>();

    pass224_k<0><<<dim3(14, 48),  512>>>(x);        // x -> s1buf (rows fwd)
    pass224_k<1><<<dim3(14, 48),  512>>>(nullptr);  // s1buf -> xh
    pass224_k<2><<<dim3(14, 384), 512>>>(nullptr);  // xh*psi0 -> s1buf (inv)
    pass224_k<3><<<dim3(14, 384), 512>>>(nullptr);  // inv + |.| -> u1h, fwd -> s2buf

    pass4fold_k<<<dim3(14, 384), 512>>>();          // col FFT + fold*psi1 -> g_foldh
    fold2_k<<<dim3(7, 48), 512>>>();                // first-order folds -> g_foldh
    blur224_k<<<432, 448>>>(x);                     // s0 + s1(j1=0) via spatial blur
    scatter2_k<<<3456, 448, SM_CHAIN>>>();          // s1(j1=1) + s2
    linear_k<<<16, 256>>>(W, bias, out);
    (void)out_size;
}